// round 4
// baseline (speedup 1.0000x reference)
#include <cuda_runtime.h>
#include <cstddef>

// Problem constants
#define BB 8
#define CC 2
#define DIN 96
#define HIN 64
#define WIN 64
#define FF 8
#define DD 3
#define HH 60
#define WW 64
#define DOUT 94        // 96 - 3 + 1
#define TT 4           // t-group size
#define NTG 24         // ceil(94/4)
#define LEAKY 0.2f

#define SMEM_FLOATS (2 * TT * 32 * 72)
#define TP(buf,t,ty,col) smem[((((buf)*TT+(t))*32+(ty))*72)+(col)]

// Precomputed bias box-sum: Bc[f][y][x] = sum over c,dd and valid 3x3 window of bias
__device__ float g_Bc[FF * HH * WW];

// One block per f. Stage 1: fold c,dd into padded smem plane. Stage 2: 3x3 box from smem.
__global__ __launch_bounds__(512) void bconv_kernel(const float* __restrict__ bias) {
    __shared__ float P[62][66];          // P[y+1][x+1] holds fold at (y,x); borders zero
    const int f = blockIdx.x;
    const int tid = threadIdx.x;
    for (int i = tid; i < 62 * 66; i += 512) (&P[0][0])[i] = 0.f;
    __syncthreads();
    for (int idx = tid; idx < HH * WW; idx += 512) {
        int x = idx & 63, y = idx >> 6;
        float s = 0.f;
        #pragma unroll
        for (int c = 0; c < CC; c++)
            #pragma unroll
            for (int dd = 0; dd < DD; dd++)
                s += bias[(((f * CC + c) * DD + dd) * HH + y) * WW + x];
        P[y + 1][x + 1] = s;
    }
    __syncthreads();
    for (int idx = tid; idx < HH * WW; idx += 512) {
        int x = idx & 63, y = idx >> 6;
        float s = P[y][x]     + P[y][x + 1]     + P[y][x + 2]
                + P[y + 1][x] + P[y + 1][x + 1] + P[y + 1][x + 2]
                + P[y + 2][x] + P[y + 2][x + 1] + P[y + 2][x + 2];
        g_Bc[(f * HH + y) * WW + x] = s;
    }
}

__device__ __forceinline__ void load_W(float2 (&Wr)[CC][DD],
                                       const float* __restrict__ wgt,
                                       int f, int ys, int x, bool vrow) {
    if (!vrow) return;
    #pragma unroll
    for (int c = 0; c < CC; c++)
        #pragma unroll
        for (int dd = 0; dd < DD; dd++)
            Wr[c][dd] = *(const float2*)(wgt + (((f * CC + c) * DD + dd) * HH + ys) * WW + x);
}

__device__ __forceinline__ void build_store(float* smem, int buf,
                                            const float2 (&Wr)[CC][DD],
                                            const float2 (&S)[CC][TT + 2],
                                            int ty, int x, int tcnt, bool vrow) {
    if (!vrow) return;
    #pragma unroll
    for (int t = 0; t < TT; t++) {
        if (t < tcnt) {
            float2 a = make_float2(0.f, 0.f);
            #pragma unroll
            for (int c = 0; c < CC; c++) {
                #pragma unroll
                for (int dd = 0; dd < DD; dd++) {
                    a.x = fmaf(S[c][t + dd].x, Wr[c][dd].x, a.x);
                    a.y = fmaf(S[c][t + dd].y, Wr[c][dd].y, a.y);
                }
            }
            *(float2*)&TP(buf, t, ty, 4 + x) = a;
        }
    }
}

// Main fused kernel, software-pipelined over f with double-buffered T.
// Grid: x = tg*2 + half (48), y = b (8). Block: 1024 threads.
// Thread (ty = tid/32 in [0,32), xi = tid%32) owns T-row ys = y0-1+ty, cols [2*xi, 2*xi+2).
// Consume phase uses an independent float4 mapping over the padded buffer.
__global__ __launch_bounds__(1024, 1)
void linconv_main(const float* __restrict__ in,
                  const float* __restrict__ wgt,
                  float* __restrict__ out) {
    extern __shared__ float smem[];

    const int b     = blockIdx.y;
    const int tg    = blockIdx.x >> 1;
    const int half  = blockIdx.x & 1;
    const int tbase = tg * TT;
    const int tcnt  = min(TT, DOUT - tbase);
    const int y0    = half * 30;
    const int tid   = threadIdx.x;
    const int ty    = tid >> 5;
    const int xi    = tid & 31;
    const int x     = xi * 2;
    const int ys    = y0 - 1 + ty;                    // T row this thread builds
    const bool vrow = (ys >= 0 && ys < HH);

    // zero both padded T buffers (pads + dead rows stay zero forever)
    for (int i = tid; i < SMEM_FLOATS; i += 1024) smem[i] = 0.f;

    // S[c][zi] = 5-row vertical sum of input at (b, c, tbase+zi, ys.., x..x+1), in registers
    float2 S[CC][TT + 2];
    #pragma unroll
    for (int c = 0; c < CC; c++) {
        #pragma unroll
        for (int zi = 0; zi < TT + 2; zi++) {
            float2 s = make_float2(0.f, 0.f);
            if (vrow && zi < tcnt + 2) {
                const float* p = in + (((size_t)(b * CC + c) * DIN + (tbase + zi)) * HIN + ys) * WIN + x;
                #pragma unroll
                for (int j = 0; j < 5; j++) {
                    float2 v = *(const float2*)(p + j * WIN);
                    s.x += v.x; s.y += v.y;
                }
            }
            S[c][zi] = s;
        }
    }

    // prologue: weights + build for f=0 into buffer 0
    float2 Wr[CC][DD];
    load_W(Wr, wgt, 0, ys, x, vrow);
    __syncthreads();          // zeroing complete before first build store
    build_store(smem, 0, Wr, S, ty, x, tcnt, vrow);
    __syncthreads();

    const int nwork = tcnt * 480;                     // 30 rows * 16 x-groups per t

    #pragma unroll 1
    for (int f = 0; f < FF; f++) {
        const int cur = f & 1;
        const bool more = (f + 1 < FF);

        // prefetch next-f weights into registers (latency drains behind consume)
        if (more) load_W(Wr, wgt, f + 1, ys, x, vrow);

        // ---- consume phase: 3x3 box sum + bias + leaky_relu + store (reads buf cur) ----
        for (int u = tid; u < nwork; u += 1024) {
            int t  = u / 480;
            int r  = u - t * 480;
            int yl = r >> 4;                          // 0..29
            int xc = (r & 15) * 4;
            const float* base = &TP(cur, t, yl, 4 + xc);   // T row yo-1 at this col
            float4 r0 = *(const float4*)(base);
            float4 r1 = *(const float4*)(base + 72);
            float4 r2 = *(const float4*)(base + 144);
            float vx = r0.x + r1.x + r2.x;
            float vy = r0.y + r1.y + r2.y;
            float vz = r0.z + r1.z + r2.z;
            float vw = r0.w + r1.w + r2.w;
            float lv = base[-1] + base[71] + base[143];   // column x-1
            float rv = base[4]  + base[76] + base[148];   // column x+4
            int yo = y0 + yl;
            float4 bc = *(const float4*)(g_Bc + (f * HH + yo) * WW + xc);
            float o0 = 0.25f * (lv + vx + vy + bc.x);
            float o1 = 0.25f * (vx + vy + vz + bc.y);
            float o2 = 0.25f * (vy + vz + vw + bc.z);
            float o3 = 0.25f * (vz + vw + rv + bc.w);
            o0 = (o0 > 0.f) ? o0 : LEAKY * o0;
            o1 = (o1 > 0.f) ? o1 : LEAKY * o1;
            o2 = (o2 > 0.f) ? o2 : LEAKY * o2;
            o3 = (o3 > 0.f) ? o3 : LEAKY * o3;
            float* op = out + ((((size_t)b * FF + f) * DOUT + (tbase + t)) * HH + yo) * WW + xc;
            *(float4*)op = make_float4(o0, o1, o2, o3);
        }

        // ---- build phase for f+1 into the other buffer (W already in registers) ----
        if (more) build_store(smem, cur ^ 1, Wr, S, ty, x, tcnt, vrow);

        __syncthreads();
    }
}

extern "C" void kernel_launch(void* const* d_in, const int* in_sizes, int n_in,
                              void* d_out, int out_size) {
    const float* in   = (const float*)d_in[0];
    const float* wgt  = (const float*)d_in[1];
    const float* bias = (const float*)d_in[2];
    float* out        = (float*)d_out;

    static bool attr_set = false;
    if (!attr_set) {
        cudaFuncSetAttribute(linconv_main,
                             cudaFuncAttributeMaxDynamicSharedMemorySize,
                             SMEM_FLOATS * sizeof(float));
        attr_set = true;
    }

    bconv_kernel<<<FF, 512>>>(bias);

    dim3 grid(NTG * 2, BB);
    linconv_main<<<grid, 1024, SMEM_FLOATS * sizeof(float)>>>(in, wgt, out);
}

// round 5
// speedup vs baseline: 1.1718x; 1.1718x over previous
#include <cuda_runtime.h>
#include <cstddef>

// Problem constants
#define BB 8
#define CC 2
#define DIN 96
#define HIN 64
#define WIN 64
#define FF 8
#define DD 3
#define HH 60
#define WW 64
#define DOUT 94        // 96 - 3 + 1
#define TT 4           // t-group size
#define NTG 24         // ceil(94/4)
#define LEAKY 0.2f

// H buffer: 2 bufs x TT x 32 rows x 64 cols (horizontally-folded T)
#define SMEM_FLOATS (2 * TT * 32 * 64)
#define HP(buf,t,ty,col) smem[((((buf)*TT+(t))*32+(ty))*64)+(col)]

// Precomputed bias box-sum: Bc[f][y][x] = sum over c,dd and valid 3x3 window of bias
__device__ float g_Bc[FF * HH * WW];

// One block per f. Stage 1: fold c,dd into padded smem plane. Stage 2: 3x3 box from smem.
__global__ __launch_bounds__(512) void bconv_kernel(const float* __restrict__ bias) {
    __shared__ float P[62][66];          // P[y+1][x+1] holds fold at (y,x); borders zero
    const int f = blockIdx.x;
    const int tid = threadIdx.x;
    for (int i = tid; i < 62 * 66; i += 512) (&P[0][0])[i] = 0.f;
    __syncthreads();
    for (int idx = tid; idx < HH * WW; idx += 512) {
        int x = idx & 63, y = idx >> 6;
        float s = 0.f;
        #pragma unroll
        for (int c = 0; c < CC; c++)
            #pragma unroll
            for (int dd = 0; dd < DD; dd++)
                s += bias[(((f * CC + c) * DD + dd) * HH + y) * WW + x];
        P[y + 1][x + 1] = s;
    }
    __syncthreads();
    for (int idx = tid; idx < HH * WW; idx += 512) {
        int x = idx & 63, y = idx >> 6;
        float s = P[y][x]     + P[y][x + 1]     + P[y][x + 2]
                + P[y + 1][x] + P[y + 1][x + 1] + P[y + 1][x + 2]
                + P[y + 2][x] + P[y + 2][x + 1] + P[y + 2][x + 2];
        g_Bc[(f * HH + y) * WW + x] = s;
    }
}

__device__ __forceinline__ void load_W(float2 (&Wr)[CC][DD],
                                       const float* __restrict__ wgt,
                                       int f, int ys, int x, bool vrow) {
    if (!vrow) return;
    #pragma unroll
    for (int c = 0; c < CC; c++)
        #pragma unroll
        for (int dd = 0; dd < DD; dd++)
            Wr[c][dd] = *(const float2*)(wgt + (((f * CC + c) * DD + dd) * HH + ys) * WW + x);
}

// Build T for one f, horizontally fold via warp shuffles, store H to smem.
// Warp == one T row (32 lanes x float2 = 64 cols); shuffles are warp-uniform.
__device__ __forceinline__ void build_store(float* smem, int buf,
                                            const float2 (&Wr)[CC][DD],
                                            const float2 (&S)[CC][TT + 2],
                                            int ty, int xi, int tcnt, bool vrow) {
    if (!vrow) return;
    #pragma unroll
    for (int t = 0; t < TT; t++) {
        if (t < tcnt) {
            float2 a = make_float2(0.f, 0.f);
            #pragma unroll
            for (int c = 0; c < CC; c++) {
                #pragma unroll
                for (int dd = 0; dd < DD; dd++) {
                    a.x = fmaf(S[c][t + dd].x, Wr[c][dd].x, a.x);
                    a.y = fmaf(S[c][t + dd].y, Wr[c][dd].y, a.y);
                }
            }
            // horizontal 3-tap fold: h[x] = T[x-1]+T[x]+T[x+1]
            float left  = __shfl_up_sync(0xffffffffu, a.y, 1);   // T[2xi-1]
            float right = __shfl_down_sync(0xffffffffu, a.x, 1); // T[2xi+2]
            if (xi == 0)  left  = 0.f;                           // SAME zero pad
            if (xi == 31) right = 0.f;
            float mid = a.x + a.y;
            float2 h = make_float2(left + mid, mid + right);
            *(float2*)&HP(buf, t, ty, 2 * xi) = h;
        }
    }
}

// Main fused kernel, software-pipelined over f with double-buffered H.
// Grid: x = tg*2 + half (48), y = b (8). Block: 1024 threads.
// Thread (ty = tid/32 in [0,32), xi = tid%32) owns T-row ys = y0-1+ty, cols [2*xi, 2*xi+2).
// Consume: out[yo][x] = leaky(0.25*(H[yo-1][x]+H[yo][x]+H[yo+1][x] + Bc)) — 3 aligned LDS.128.
__global__ __launch_bounds__(1024, 1)
void linconv_main(const float* __restrict__ in,
                  const float* __restrict__ wgt,
                  float* __restrict__ out) {
    extern __shared__ float smem[];

    const int b     = blockIdx.y;
    const int tg    = blockIdx.x >> 1;
    const int half  = blockIdx.x & 1;
    const int tbase = tg * TT;
    const int tcnt  = min(TT, DOUT - tbase);
    const int y0    = half * 30;
    const int tid   = threadIdx.x;
    const int ty    = tid >> 5;
    const int xi    = tid & 31;
    const int x     = xi * 2;
    const int ys    = y0 - 1 + ty;                    // T row this thread builds
    const bool vrow = (ys >= 0 && ys < HH);

    // zero both H buffers (dead rows stay zero forever = vertical SAME pad)
    for (int i = tid; i < SMEM_FLOATS; i += 1024) smem[i] = 0.f;

    // S[c][zi] = 5-row vertical sum of input at (b, c, tbase+zi, ys.., x..x+1), in registers
    float2 S[CC][TT + 2];
    #pragma unroll
    for (int c = 0; c < CC; c++) {
        #pragma unroll
        for (int zi = 0; zi < TT + 2; zi++) {
            float2 s = make_float2(0.f, 0.f);
            if (vrow && zi < tcnt + 2) {
                const float* p = in + (((size_t)(b * CC + c) * DIN + (tbase + zi)) * HIN + ys) * WIN + x;
                #pragma unroll
                for (int j = 0; j < 5; j++) {
                    float2 v = *(const float2*)(p + j * WIN);
                    s.x += v.x; s.y += v.y;
                }
            }
            S[c][zi] = s;
        }
    }

    // prologue: weights + build for f=0 into buffer 0
    float2 Wr[CC][DD];
    load_W(Wr, wgt, 0, ys, x, vrow);
    __syncthreads();          // zeroing complete before first build store
    build_store(smem, 0, Wr, S, ty, xi, tcnt, vrow);
    __syncthreads();

    const int nwork = tcnt * 480;                     // 30 rows * 16 x-groups per t

    #pragma unroll 1
    for (int f = 0; f < FF; f++) {
        const int cur = f & 1;
        const bool more = (f + 1 < FF);

        // prefetch next-f weights into registers (latency drains behind consume)
        if (more) load_W(Wr, wgt, f + 1, ys, x, vrow);

        // ---- consume phase: vertical 3-sum of H + bias + leaky_relu + store ----
        for (int u = tid; u < nwork; u += 1024) {
            int t  = u / 480;
            int r  = u - t * 480;
            int yl = r >> 4;                          // 0..29
            int xc = (r & 15) * 4;
            const float* base = &HP(cur, t, yl, xc);  // H rows yl, yl+1, yl+2
            float4 r0 = *(const float4*)(base);
            float4 r1 = *(const float4*)(base + 64);
            float4 r2 = *(const float4*)(base + 128);
            int yo = y0 + yl;
            float4 bc = *(const float4*)(g_Bc + (f * HH + yo) * WW + xc);
            float o0 = 0.25f * (r0.x + r1.x + r2.x + bc.x);
            float o1 = 0.25f * (r0.y + r1.y + r2.y + bc.y);
            float o2 = 0.25f * (r0.z + r1.z + r2.z + bc.z);
            float o3 = 0.25f * (r0.w + r1.w + r2.w + bc.w);
            o0 = (o0 > 0.f) ? o0 : LEAKY * o0;
            o1 = (o1 > 0.f) ? o1 : LEAKY * o1;
            o2 = (o2 > 0.f) ? o2 : LEAKY * o2;
            o3 = (o3 > 0.f) ? o3 : LEAKY * o3;
            float* op = out + ((((size_t)b * FF + f) * DOUT + (tbase + t)) * HH + yo) * WW + xc;
            *(float4*)op = make_float4(o0, o1, o2, o3);
        }

        // ---- build phase for f+1 into the other buffer (W already in registers) ----
        if (more) build_store(smem, cur ^ 1, Wr, S, ty, xi, tcnt, vrow);

        __syncthreads();
    }
}

extern "C" void kernel_launch(void* const* d_in, const int* in_sizes, int n_in,
                              void* d_out, int out_size) {
    const float* in   = (const float*)d_in[0];
    const float* wgt  = (const float*)d_in[1];
    const float* bias = (const float*)d_in[2];
    float* out        = (float*)d_out;

    static bool attr_set = false;
    if (!attr_set) {
        cudaFuncSetAttribute(linconv_main,
                             cudaFuncAttributeMaxDynamicSharedMemorySize,
                             SMEM_FLOATS * sizeof(float));
        attr_set = true;
    }

    bconv_kernel<<<FF, 512>>>(bias);

    dim3 grid(NTG * 2, BB);
    linconv_main<<<grid, 1024, SMEM_FLOATS * sizeof(float)>>>(in, wgt, out);
}

// round 7
// speedup vs baseline: 1.2736x; 1.0869x over previous
#include <cuda_runtime.h>
#include <cstddef>

// Problem constants
#define BB 8
#define CC 2
#define DIN 96
#define HIN 64
#define WIN 64
#define FF 8
#define DD 3
#define HH 60
#define WW 64
#define DOUT 94        // 96 - 3 + 1
#define TT 4           // t-group size
#define NTG 24         // ceil(94/4)
#define LEAKY 0.2f

// H buffer: 2 bufs x TT x 32 rows x 64 cols (horizontally-folded T)
#define BUFSTRIDE (TT * 32 * 64)          // 8192 floats per buffer
#define SMEM_FLOATS (2 * BUFSTRIDE)
#define OUT_FSTRIDE (DOUT * HH * WW)      // out advance per f
#define BC_FSTRIDE (HH * WW)              // g_Bc advance per f
#define W_FSTRIDE (CC * DD * HH * WW)     // weight advance per f

// Precomputed bias box-sum: Bc[f][y][x] = sum over c,dd and valid 3x3 window of bias
__device__ float g_Bc[FF * HH * WW];

// Grid (FF, 8): block (f, g) computes rows y in [8g, min(8g+8, HH)). Haloed fold rows in smem.
__global__ __launch_bounds__(256) void bconv_kernel(const float* __restrict__ bias) {
    __shared__ float P[10][66];           // fold rows 8g-1 .. 8g+8, cols padded
    const int f = blockIdx.x;
    const int g = blockIdx.y;
    const int tid = threadIdx.x;
    for (int i = tid; i < 10 * 66; i += 256) (&P[0][0])[i] = 0.f;
    __syncthreads();
    for (int idx = tid; idx < 10 * 64; idx += 256) {
        int x = idx & 63, row = idx >> 6;
        int yy = 8 * g - 1 + row;
        if (yy >= 0 && yy < HH) {
            float s = 0.f;
            #pragma unroll
            for (int c = 0; c < CC; c++)
                #pragma unroll
                for (int dd = 0; dd < DD; dd++)
                    s += bias[(((f * CC + c) * DD + dd) * HH + yy) * WW + x];
            P[row][x + 1] = s;
        }
    }
    __syncthreads();
    for (int idx = tid; idx < 8 * 64; idx += 256) {
        int x = idx & 63, r = idx >> 6;
        int y = 8 * g + r;
        if (y >= HH) continue;            // HH=60 not divisible by 8: skip rows 60..63
        float s = P[r][x]     + P[r][x + 1]     + P[r][x + 2]
                + P[r + 1][x] + P[r + 1][x + 1] + P[r + 1][x + 2]
                + P[r + 2][x] + P[r + 2][x + 1] + P[r + 2][x + 2];
        g_Bc[(f * HH + y) * WW + x] = s;
    }
}

// Load 6 weight float2's from a per-thread base pointer (advanced by W_FSTRIDE per f).
__device__ __forceinline__ void load_W(float2 (&Wr)[CC][DD],
                                       const float* __restrict__ wp, bool vrow) {
    if (!vrow) return;
    #pragma unroll
    for (int c = 0; c < CC; c++)
        #pragma unroll
        for (int dd = 0; dd < DD; dd++)
            Wr[c][dd] = *(const float2*)(wp + (c * DD + dd) * (HH * WW));
}

// Build T for one f, horizontally fold via warp shuffles, store H to smem.
// t >= tcnt writes zeros (S zeroed there) and is never read by consume — harmless.
__device__ __forceinline__ void build_store(float* __restrict__ hdst,
                                            const float2 (&Wr)[CC][DD],
                                            const float2 (&S)[CC][TT + 2],
                                            int xi, bool vrow) {
    if (!vrow) return;
    #pragma unroll
    for (int t = 0; t < TT; t++) {
        float2 a = make_float2(0.f, 0.f);
        #pragma unroll
        for (int c = 0; c < CC; c++) {
            #pragma unroll
            for (int dd = 0; dd < DD; dd++) {
                a.x = fmaf(S[c][t + dd].x, Wr[c][dd].x, a.x);
                a.y = fmaf(S[c][t + dd].y, Wr[c][dd].y, a.y);
            }
        }
        // horizontal 3-tap fold: h[x] = T[x-1]+T[x]+T[x+1], SAME zero pad at edges
        float left  = __shfl_up_sync(0xffffffffu, a.y, 1);
        float right = __shfl_down_sync(0xffffffffu, a.x, 1);
        if (xi == 0)  left  = 0.f;
        if (xi == 31) right = 0.f;
        float mid = a.x + a.y;
        *(float2*)(hdst + t * (32 * 64)) = make_float2(left + mid, mid + right);
    }
}

// Main fused kernel, software-pipelined over f with double-buffered H.
// Grid: x = tg*2 + half (48), y = b (8). Block: 1024 threads.
// Build: thread (ty=tid/32, xi=tid%32) owns T-row ys=y0-1+ty, cols [2xi, 2xi+2).
// Consume: each thread has <=2 fixed work items (float4 each); offsets precomputed,
// advanced by constant strides per f.
__global__ __launch_bounds__(1024, 1)
void linconv_main(const float* __restrict__ in,
                  const float* __restrict__ wgt,
                  float* __restrict__ out) {
    extern __shared__ float smem[];

    const int b     = blockIdx.y;
    const int tg    = blockIdx.x >> 1;
    const int half  = blockIdx.x & 1;
    const int tbase = tg * TT;
    const int tcnt  = min(TT, DOUT - tbase);
    const int y0    = half * 30;
    const int tid   = threadIdx.x;
    const int ty    = tid >> 5;
    const int xi    = tid & 31;
    const int x     = xi * 2;
    const int ys    = y0 - 1 + ty;                    // T row this thread builds
    const bool vrow = (ys >= 0 && ys < HH);

    // zero both H buffers (dead rows stay zero forever = vertical SAME pad)
    for (int i = tid; i < SMEM_FLOATS; i += 1024) smem[i] = 0.f;

    // S[c][zi] = 5-row vertical sum of input at (b, c, tbase+zi, ys.., x..x+1)
    float2 S[CC][TT + 2];
    #pragma unroll
    for (int c = 0; c < CC; c++) {
        #pragma unroll
        for (int zi = 0; zi < TT + 2; zi++) {
            float2 s = make_float2(0.f, 0.f);
            if (vrow && zi < tcnt + 2) {
                const float* p = in + (((size_t)(b * CC + c) * DIN + (tbase + zi)) * HIN + ys) * WIN + x;
                #pragma unroll
                for (int j = 0; j < 5; j++) {
                    float2 v = *(const float2*)(p + j * WIN);
                    s.x += v.x; s.y += v.y;
                }
            }
            S[c][zi] = s;
        }
    }

    // ---- precompute consume work items (fixed across f) ----
    const int nwork = tcnt * 480;                     // 30 rows * 16 x-groups per t
    int  soff0 = 0, soff1 = 0;                        // smem offset within buffer
    const float* bcp0 = g_Bc; const float* bcp1 = g_Bc;
    float* outp0 = out; float* outp1 = out;
    const bool v0 = (tid < nwork);
    const bool v1 = (tid + 1024 < nwork);
    {
        int u = tid;
        int t = u / 480, r = u - t * 480;
        int yl = r >> 4, xc = (r & 15) * 4;
        soff0 = (t * 32 + yl) * 64 + xc;
        bcp0  = g_Bc + (y0 + yl) * WW + xc;
        outp0 = out + ((((size_t)b * FF) * DOUT + tbase + t) * HH + y0 + yl) * WW + xc;
        u = tid + 1024;
        t = u / 480; r = u - t * 480;
        yl = r >> 4; xc = (r & 15) * 4;
        soff1 = (t * 32 + yl) * 64 + xc;
        bcp1  = g_Bc + (y0 + yl) * WW + xc;
        outp1 = out + ((((size_t)b * FF) * DOUT + tbase + t) * HH + y0 + yl) * WW + xc;
    }

    // per-thread weight base pointer (advanced per f)
    const float* wp = wgt + ys * WW + x;
    float* const hbase = smem + ty * 64 + 2 * xi;     // build dst, + buf*BUFSTRIDE

    // prologue: weights + build for f=0 into buffer 0
    float2 Wr[CC][DD];
    load_W(Wr, wp, vrow);
    __syncthreads();          // zeroing complete before first build store
    build_store(hbase, Wr, S, xi, vrow);
    __syncthreads();

    #pragma unroll 1
    for (int f = 0; f < FF; f++) {
        const int cur = f & 1;
        const bool more = (f + 1 < FF);

        // prefetch next-f weights into registers (latency drains behind consume)
        if (more) load_W(Wr, wp + (f + 1) * W_FSTRIDE, vrow);

        // ---- consume phase: vertical 3-sum of H + bias + leaky_relu + store ----
        const float* hb = smem + cur * BUFSTRIDE;
        if (v0) {
            float4 bc = *(const float4*)bcp0;
            const float* base = hb + soff0;
            float4 r0 = *(const float4*)(base);
            float4 r1 = *(const float4*)(base + 64);
            float4 r2 = *(const float4*)(base + 128);
            float o0 = 0.25f * (r0.x + r1.x + r2.x + bc.x);
            float o1 = 0.25f * (r0.y + r1.y + r2.y + bc.y);
            float o2 = 0.25f * (r0.z + r1.z + r2.z + bc.z);
            float o3 = 0.25f * (r0.w + r1.w + r2.w + bc.w);
            o0 = (o0 > 0.f) ? o0 : LEAKY * o0;
            o1 = (o1 > 0.f) ? o1 : LEAKY * o1;
            o2 = (o2 > 0.f) ? o2 : LEAKY * o2;
            o3 = (o3 > 0.f) ? o3 : LEAKY * o3;
            *(float4*)outp0 = make_float4(o0, o1, o2, o3);
        }
        if (v1) {
            float4 bc = *(const float4*)bcp1;
            const float* base = hb + soff1;
            float4 r0 = *(const float4*)(base);
            float4 r1 = *(const float4*)(base + 64);
            float4 r2 = *(const float4*)(base + 128);
            float o0 = 0.25f * (r0.x + r1.x + r2.x + bc.x);
            float o1 = 0.25f * (r0.y + r1.y + r2.y + bc.y);
            float o2 = 0.25f * (r0.z + r1.z + r2.z + bc.z);
            float o3 = 0.25f * (r0.w + r1.w + r2.w + bc.w);
            o0 = (o0 > 0.f) ? o0 : LEAKY * o0;
            o1 = (o1 > 0.f) ? o1 : LEAKY * o1;
            o2 = (o2 > 0.f) ? o2 : LEAKY * o2;
            o3 = (o3 > 0.f) ? o3 : LEAKY * o3;
            *(float4*)outp1 = make_float4(o0, o1, o2, o3);
        }
        bcp0 += BC_FSTRIDE;  bcp1 += BC_FSTRIDE;
        outp0 += OUT_FSTRIDE; outp1 += OUT_FSTRIDE;

        // ---- build phase for f+1 into the other buffer (W already in registers) ----
        if (more) build_store(hbase + (cur ^ 1) * BUFSTRIDE, Wr, S, xi, vrow);

        __syncthreads();
    }
}

extern "C" void kernel_launch(void* const* d_in, const int* in_sizes, int n_in,
                              void* d_out, int out_size) {
    const float* in   = (const float*)d_in[0];
    const float* wgt  = (const float*)d_in[1];
    const float* bias = (const float*)d_in[2];
    float* out        = (float*)d_out;

    static bool attr_set = false;
    if (!attr_set) {
        cudaFuncSetAttribute(linconv_main,
                             cudaFuncAttributeMaxDynamicSharedMemorySize,
                             SMEM_FLOATS * sizeof(float));
        attr_set = true;
    }

    dim3 bgrid(FF, 8);
    bconv_kernel<<<bgrid, 256>>>(bias);

    dim3 grid(NTG * 2, BB);
    linconv_main<<<grid, 1024, SMEM_FLOATS * sizeof(float)>>>(in, wgt, out);
}